// round 2
// baseline (speedup 1.0000x reference)
#include <cuda_runtime.h>
#include <cstdint>

#define B_   2
#define S_   2048
#define DIM_ 1024
#define NH_  8
#define MROWS (B_*S_)           // 4096
#define QD   128                // q/k head dim (96 nope + 32 rope)
#define VD   256                // v head dim

// ---------------- scratch (device globals; no allocation allowed) ----------------
__device__ float g_cq  [MROWS*128];
__device__ float g_ckv [MROWS*192];
__device__ float g_q   [MROWS*1024];
__device__ float g_kv  [(size_t)MROWS*2560];
__device__ float g_Qs  [(size_t)B_*NH_*S_*QD];
__device__ float g_Ks  [(size_t)B_*NH_*S_*QD];
__device__ float g_Vs  [(size_t)B_*NH_*S_*VD];
__device__ float g_attn[(size_t)MROWS*2048];

// ---------------- generic SGEMM: C[M,N] = A[M,K(lda)] @ B[K,N] + bias ----------------
__global__ void __launch_bounds__(256) sgemm_bias(
    const float* __restrict__ A, const float* __restrict__ Bm,
    const float* __restrict__ bias, float* __restrict__ C,
    int M, int N, int K, int lda)
{
    __shared__ float As[8][128];
    __shared__ float Bs[8][128];

    const int tid = threadIdx.x;
    const int tx  = tid & 15;
    const int ty  = tid >> 4;
    const int bm  = blockIdx.y * 128;
    const int bn  = blockIdx.x * 128;

    const int arow = tid >> 1, acol = (tid & 1) << 2;   // A: 128 rows x 8 cols
    const int brow = tid >> 5, bcol = (tid & 31) << 2;  // B: 8 rows x 128 cols

    float acc[8][8];
#pragma unroll
    for (int i = 0; i < 8; i++)
#pragma unroll
        for (int j = 0; j < 8; j++) acc[i][j] = 0.f;

    for (int k0 = 0; k0 < K; k0 += 8) {
        float4 av = *(const float4*)&A[(size_t)(bm + arow) * lda + k0 + acol];
        float4 bv = make_float4(0.f, 0.f, 0.f, 0.f);
        if (bn + bcol < N)
            bv = *(const float4*)&Bm[(size_t)(k0 + brow) * N + bn + bcol];

        __syncthreads();
        As[acol + 0][arow] = av.x;
        As[acol + 1][arow] = av.y;
        As[acol + 2][arow] = av.z;
        As[acol + 3][arow] = av.w;
        *(float4*)&Bs[brow][bcol] = bv;
        __syncthreads();

#pragma unroll
        for (int kk = 0; kk < 8; kk++) {
            float4 a0 = *(const float4*)&As[kk][ty * 4];
            float4 a1 = *(const float4*)&As[kk][64 + ty * 4];
            float4 b0 = *(const float4*)&Bs[kk][tx * 4];
            float4 b1 = *(const float4*)&Bs[kk][64 + tx * 4];
            float a[8] = {a0.x, a0.y, a0.z, a0.w, a1.x, a1.y, a1.z, a1.w};
            float b[8] = {b0.x, b0.y, b0.z, b0.w, b1.x, b1.y, b1.z, b1.w};
#pragma unroll
            for (int i = 0; i < 8; i++)
#pragma unroll
                for (int j = 0; j < 8; j++)
                    acc[i][j] += a[i] * b[j];
        }
    }

#pragma unroll
    for (int i = 0; i < 8; i++) {
        int row = bm + ((i < 4) ? (ty * 4 + i) : (64 + ty * 4 + i - 4));
#pragma unroll
        for (int j = 0; j < 8; j++) {
            int col = bn + ((j < 4) ? (tx * 4 + j) : (64 + tx * 4 + j - 4));
            if (col < N)
                C[(size_t)row * N + col] = acc[i][j] + bias[col];
        }
    }
}

// ---------------- RMSNorm in place over first `blockDim.x` cols of each row ----------------
__global__ void rmsnorm_kernel(float* __restrict__ buf, const float* __restrict__ w,
                               int stride)
{
    const int row = blockIdx.x;
    const int tid = threadIdx.x;      // == ncols == 128
    float v = buf[(size_t)row * stride + tid];
    float s = v * v;
#pragma unroll
    for (int o = 16; o; o >>= 1) s += __shfl_xor_sync(0xffffffffu, s, o);
    __shared__ float ws[4];
    if ((tid & 31) == 0) ws[tid >> 5] = s;
    __syncthreads();
    float tot = ws[0] + ws[1] + ws[2] + ws[3];
    float rr = rsqrtf(tot / (float)blockDim.x + 1e-8f);
    buf[(size_t)row * stride + tid] = w[tid] * v * rr;
}

// ---------------- interleaved RoPE in place ----------------
__global__ void rope_kernel(float* __restrict__ buf, const int* __restrict__ pos,
                            int stride, int col_off, int hd)
{
    const int row = blockIdx.x;
    const int tid = threadIdx.x;              // nheads*hd/2 threads
    const int half = hd >> 1;
    const int h = tid / half, i = tid % half;
    float p = (float)pos[row];
    float freq = powf(10000.0f, -2.0f * (float)i / (float)hd);
    float ang = p * freq;
    float sn, cs;
    sincosf(ang, &sn, &cs);
    size_t base = (size_t)row * stride + col_off + h * hd + 2 * i;
    float xe = buf[base], xo = buf[base + 1];
    buf[base]     = xe * cs - xo * sn;
    buf[base + 1] = xe * sn + xo * cs;
}

// ---------------- repack to contiguous [b,h,s,d] ----------------
__global__ void repack_kernel(const float* __restrict__ q, const float* __restrict__ kv,
                              const float* __restrict__ ckv,
                              float* __restrict__ Qo, float* __restrict__ Ko,
                              float* __restrict__ Vo)
{
    const int bhs = blockIdx.x;               // 16*2048
    const int d   = threadIdx.x;              // 128
    const int s   = bhs & (S_ - 1);
    const int bh  = bhs >> 11;
    const int h   = bh & 7;
    const int b   = bh >> 3;
    const size_t row = (size_t)b * S_ + s;
    const size_t o128 = (size_t)bhs * 128, o256 = (size_t)bhs * 256;

    Qo[o128 + d] = (d < 96) ? q[row * 1024 + h * 96 + d]
                            : q[row * 1024 + 768 + h * 32 + (d - 96)];
    Ko[o128 + d] = (d < 64) ? kv[row * 2560 + h * 64 + d]
                            : ckv[row * 192 + 128 + (d - 64)];
    Vo[o256 + d]       = kv[row * 2560 + 512 + (size_t)h * 256 + d];
    Vo[o256 + 128 + d] = kv[row * 2560 + 512 + (size_t)h * 256 + 128 + d];
}

// ---------------- flash attention: BM=32 q-rows, BN=32 k-rows ----------------
// smem: sQ 32x132, sK 32x132, sV 32x256, sP 32x33  => 70784 B dynamic
__global__ void __launch_bounds__(256) flash_attn(
    const float* __restrict__ Q, const float* __restrict__ K,
    const float* __restrict__ V, float* __restrict__ O)
{
    extern __shared__ float sm[];
    float* sQ = sm;                    // 32*132
    float* sK = sQ + 32 * 132;         // 32*132
    float* sV = sK + 32 * 132;         // 32*256
    float* sP = sV + 32 * 256;         // 32*33

    const int tid = threadIdx.x;
    const int bh  = blockIdx.y;        // 0..15
    const int qt  = blockIdx.x;        // 0..63
    const int r   = tid >> 3;          // q row in tile (0..31)
    const int g   = tid & 7;           // 8 threads per row
    const float scale = 0.08838834764831845f;   // 1/sqrt(128)

    const float* Qg = Q + ((size_t)bh * S_ + qt * 32) * QD;
    for (int i = tid; i < 32 * 128; i += 256)
        sQ[(i >> 7) * 132 + (i & 127)] = Qg[i];

    float acc[32];
#pragma unroll
    for (int j = 0; j < 32; j++) acc[j] = 0.f;
    float m = -1e30f, l = 0.f;

    for (int kt = 0; kt < S_ / 32; kt++) {
        __syncthreads();
        const float* Kg = K + ((size_t)bh * S_ + kt * 32) * QD;
        for (int i = tid; i < 32 * 128; i += 256)
            sK[(i >> 7) * 132 + (i & 127)] = Kg[i];
        const float* Vg = V + ((size_t)bh * S_ + kt * 32) * VD;
        for (int i = tid; i < 32 * 256; i += 256)
            sV[i] = Vg[i];
        __syncthreads();

        // ---- scores: thread computes s[r][g + 8j], j<4 ----
        float sc[4] = {0.f, 0.f, 0.f, 0.f};
#pragma unroll 8
        for (int d = 0; d < 128; d += 4) {
            float4 qv = *(const float4*)&sQ[r * 132 + d];
#pragma unroll
            for (int j = 0; j < 4; j++) {
                float4 kv4 = *(const float4*)&sK[(g + 8 * j) * 132 + d];
                sc[j] += qv.x * kv4.x + qv.y * kv4.y + qv.z * kv4.z + qv.w * kv4.w;
            }
        }
#pragma unroll
        for (int j = 0; j < 4; j++) sc[j] *= scale;

        // ---- online softmax (reduce over 8 threads of the row) ----
        float tmax = fmaxf(fmaxf(sc[0], sc[1]), fmaxf(sc[2], sc[3]));
#pragma unroll
        for (int o = 4; o; o >>= 1)
            tmax = fmaxf(tmax, __shfl_xor_sync(0xffffffffu, tmax, o));
        float mnew  = fmaxf(m, tmax);
        float alpha = __expf(m - mnew);
        float rs = 0.f;
#pragma unroll
        for (int j = 0; j < 4; j++) {
            float p = __expf(sc[j] - mnew);
            sP[r * 33 + g + 8 * j] = p;
            rs += p;
        }
#pragma unroll
        for (int o = 4; o; o >>= 1)
            rs += __shfl_xor_sync(0xffffffffu, rs, o);
        l = l * alpha + rs;
        m = mnew;
#pragma unroll
        for (int j = 0; j < 32; j++) acc[j] *= alpha;
        __syncwarp();

        // ---- PV: acc[c] += p[r][k] * V[k][c], c = g*4 + 32j + i ----
#pragma unroll 4
        for (int k = 0; k < 32; k++) {
            float p = sP[r * 33 + k];
#pragma unroll
            for (int j = 0; j < 8; j++) {
                float4 v = *(const float4*)&sV[k * 256 + g * 4 + 32 * j];
                acc[4 * j + 0] += p * v.x;
                acc[4 * j + 1] += p * v.y;
                acc[4 * j + 2] += p * v.z;
                acc[4 * j + 3] += p * v.w;
            }
        }
    }

    const float inv = 1.0f / l;
    const int b = bh >> 3, h = bh & 7;
    const size_t orow = ((size_t)b * S_ + qt * 32 + r) * 2048;
#pragma unroll
    for (int j = 0; j < 8; j++)
#pragma unroll
        for (int i = 0; i < 4; i++)
            O[orow + h * 256 + g * 4 + 32 * j + i] = acc[4 * j + i] * inv;
}

// ---------------- launch ----------------
extern "C" void kernel_launch(void* const* d_in, const int* in_sizes, int n_in,
                              void* d_out, int out_size)
{
    const float* x         = (const float*)d_in[0];
    const int*   pos       = (const int*)  d_in[1];
    const float* w_dq_w    = (const float*)d_in[2];
    const float* w_dq_b    = (const float*)d_in[3];
    const float* q_norm_w  = (const float*)d_in[4];
    const float* w_uq_w    = (const float*)d_in[5];
    const float* w_uq_b    = (const float*)d_in[6];
    const float* w_dkv_w   = (const float*)d_in[7];
    const float* w_dkv_b   = (const float*)d_in[8];
    const float* kv_norm_w = (const float*)d_in[9];
    const float* w_ukv_w   = (const float*)d_in[10];
    const float* w_ukv_b   = (const float*)d_in[11];
    const float* w_o_w     = (const float*)d_in[12];
    const float* w_o_b     = (const float*)d_in[13];
    float* out = (float*)d_out;

    float *cq, *ckv, *q, *kv, *Qs, *Ks, *Vs, *attn;
    cudaGetSymbolAddress((void**)&cq,   g_cq);
    cudaGetSymbolAddress((void**)&ckv,  g_ckv);
    cudaGetSymbolAddress((void**)&q,    g_q);
    cudaGetSymbolAddress((void**)&kv,   g_kv);
    cudaGetSymbolAddress((void**)&Qs,   g_Qs);
    cudaGetSymbolAddress((void**)&Ks,   g_Ks);
    cudaGetSymbolAddress((void**)&Vs,   g_Vs);
    cudaGetSymbolAddress((void**)&attn, g_attn);

    const int M = MROWS;

    // down-projections from x
    sgemm_bias<<<dim3(1, 32), 256>>>(x, w_dq_w,  w_dq_b,  cq,  M, 128, 1024, 1024);
    sgemm_bias<<<dim3(2, 32), 256>>>(x, w_dkv_w, w_dkv_b, ckv, M, 192, 1024, 1024);

    // norms + k rope
    rmsnorm_kernel<<<M, 128>>>(cq,  q_norm_w,  128);
    rmsnorm_kernel<<<M, 128>>>(ckv, kv_norm_w, 192);
    rope_kernel<<<M, 32>>>(ckv, pos, 192, 128, 64);   // 1 head x 64

    // up-projections
    sgemm_bias<<<dim3(8, 32), 256>>>(cq,  w_uq_w,  w_uq_b,  q,  M, 1024, 128, 128);
    rope_kernel<<<M, 128>>>(q, pos, 1024, 768, 32);   // 8 heads x 32
    sgemm_bias<<<dim3(20, 32), 256>>>(ckv, w_ukv_w, w_ukv_b, kv, M, 2560, 128, 192);

    // gather into contiguous per-head layout
    repack_kernel<<<B_ * NH_ * S_, 128>>>(q, kv, ckv, Qs, Ks, Vs);

    // attention
    cudaFuncSetAttribute(flash_attn, cudaFuncAttributeMaxDynamicSharedMemorySize, 70784);
    flash_attn<<<dim3(S_ / 32, B_ * NH_), 256, 70784>>>(Qs, Ks, Vs, attn);

    // output projection
    sgemm_bias<<<dim3(8, 32), 256>>>(attn, w_o_w, w_o_b, out, M, 1024, 2048, 2048);
}

// round 4
// speedup vs baseline: 2.9360x; 2.9360x over previous
#include <cuda_runtime.h>
#include <cstdint>

#define B_   2
#define S_   2048
#define DIM_ 1024
#define NH_  8
#define MROWS (B_*S_)           // 4096
#define QD   128
#define VD   256

// ---------------- scratch ----------------
__device__ float g_cq  [MROWS*128];
__device__ float g_ckv [MROWS*192];
__device__ float g_q   [MROWS*1024];
__device__ float g_kv  [(size_t)MROWS*2560];
__device__ float g_Qs  [(size_t)B_*NH_*S_*QD];
__device__ float g_Ks  [(size_t)B_*NH_*S_*QD];
__device__ float g_Vs  [(size_t)B_*NH_*S_*VD];
__device__ float g_attn[(size_t)MROWS*2048];

// ---------------- tf32 helpers ----------------
__device__ __forceinline__ float f2tf(float x) {
    uint32_t u;
    asm("cvt.rna.tf32.f32 %0, %1;" : "=r"(u) : "f"(x));
    return __uint_as_float(u);
}

__device__ __forceinline__ void mma8(float& d0, float& d1, float& d2, float& d3,
                                     float a0, float a1, float a2, float a3,
                                     float b0, float b1)
{
    uint32_t A0 = __float_as_uint(a0), A1 = __float_as_uint(a1);
    uint32_t A2 = __float_as_uint(a2), A3 = __float_as_uint(a3);
    uint32_t B0 = __float_as_uint(b0), B1 = __float_as_uint(b1);
    asm volatile(
        "mma.sync.aligned.m16n8k8.row.col.f32.tf32.tf32.f32 "
        "{%0,%1,%2,%3},{%4,%5,%6,%7},{%8,%9},{%0,%1,%2,%3};\n"
        : "+f"(d0), "+f"(d1), "+f"(d2), "+f"(d3)
        : "r"(A0), "r"(A1), "r"(A2), "r"(A3), "r"(B0), "r"(B1));
}

// ---------------- fp32 SGEMM (kept for the two down-projections) ----------------
__global__ void __launch_bounds__(256) sgemm_bias(
    const float* __restrict__ A, const float* __restrict__ Bm,
    const float* __restrict__ bias, float* __restrict__ C,
    int M, int N, int K, int lda)
{
    __shared__ float As[8][128];
    __shared__ float Bs[8][128];

    const int tid = threadIdx.x;
    const int tx  = tid & 15;
    const int ty  = tid >> 4;
    const int bm  = blockIdx.y * 128;
    const int bn  = blockIdx.x * 128;

    const int arow = tid >> 1, acol = (tid & 1) << 2;
    const int brow = tid >> 5, bcol = (tid & 31) << 2;

    float acc[8][8];
#pragma unroll
    for (int i = 0; i < 8; i++)
#pragma unroll
        for (int j = 0; j < 8; j++) acc[i][j] = 0.f;

    for (int k0 = 0; k0 < K; k0 += 8) {
        float4 av = *(const float4*)&A[(size_t)(bm + arow) * lda + k0 + acol];
        float4 bv = make_float4(0.f, 0.f, 0.f, 0.f);
        if (bn + bcol < N)
            bv = *(const float4*)&Bm[(size_t)(k0 + brow) * N + bn + bcol];

        __syncthreads();
        As[acol + 0][arow] = av.x;
        As[acol + 1][arow] = av.y;
        As[acol + 2][arow] = av.z;
        As[acol + 3][arow] = av.w;
        *(float4*)&Bs[brow][bcol] = bv;
        __syncthreads();

#pragma unroll
        for (int kk = 0; kk < 8; kk++) {
            float4 a0 = *(const float4*)&As[kk][ty * 4];
            float4 a1 = *(const float4*)&As[kk][64 + ty * 4];
            float4 b0 = *(const float4*)&Bs[kk][tx * 4];
            float4 b1 = *(const float4*)&Bs[kk][64 + tx * 4];
            float a[8] = {a0.x, a0.y, a0.z, a0.w, a1.x, a1.y, a1.z, a1.w};
            float b[8] = {b0.x, b0.y, b0.z, b0.w, b1.x, b1.y, b1.z, b1.w};
#pragma unroll
            for (int i = 0; i < 8; i++)
#pragma unroll
                for (int j = 0; j < 8; j++)
                    acc[i][j] += a[i] * b[j];
        }
    }

#pragma unroll
    for (int i = 0; i < 8; i++) {
        int row = bm + ((i < 4) ? (ty * 4 + i) : (64 + ty * 4 + i - 4));
#pragma unroll
        for (int j = 0; j < 8; j++) {
            int col = bn + ((j < 4) ? (tx * 4 + j) : (64 + tx * 4 + j - 4));
            if (col < N)
                C[(size_t)row * N + col] = acc[i][j] + bias[col];
        }
    }
}

// ---------------- tf32 tensor-core GEMM: C[M,N] = A[M,K(lda)]@B[K,N] + bias ----------------
// 128x128 tile, BK=16, 8 warps in 2(m) x 4(n), each warp 64x32.
__global__ void __launch_bounds__(256) gemm_tf32(
    const float* __restrict__ A, const float* __restrict__ Bm,
    const float* __restrict__ bias, float* __restrict__ C,
    int M, int N, int K, int lda)
{
    __shared__ float As[128][20];   // [row][k], pad 16->20 (conflict-free frag reads)
    __shared__ float Bs[16][136];   // [k][col], pad 128->136

    const int tid  = threadIdx.x;
    const int wid  = tid >> 5;
    const int lane = tid & 31;
    const int bm   = blockIdx.y * 128;
    const int bn   = blockIdx.x * 128;
    const int wm   = (wid >> 2) * 64;   // 0 or 64
    const int wn   = (wid & 3) * 32;    // 0,32,64,96
    const int r    = lane >> 2;
    const int c    = lane & 3;

    float acc[4][4][4];
#pragma unroll
    for (int i = 0; i < 4; i++)
#pragma unroll
        for (int j = 0; j < 4; j++)
#pragma unroll
            for (int k = 0; k < 4; k++) acc[i][j][k] = 0.f;

    // load maps
    const int ar = tid >> 1, ac4 = (tid & 1) << 3;         // A: 2 float4 per thread -> rows 0..127, cols 0/8
    const int br = tid >> 4, bc4 = (tid & 15) << 3;        // B: rows 0..15, 2 float4 at cols bc4, bc4+4? (see below)

    for (int k0 = 0; k0 < K; k0 += 16) {
        // A tile: 128x16 = 512 float4; thread loads 2 (cols ac4..ac4+3 and ac4+4..ac4+7)
        float4 av0 = *(const float4*)&A[(size_t)(bm + ar) * lda + k0 + ac4];
        float4 av1 = *(const float4*)&A[(size_t)(bm + ar) * lda + k0 + ac4 + 4];
        // B tile: 16x128 = 512 float4; thread loads 2 (cols bc4, bc4+4)
        float4 bv0 = make_float4(0.f, 0.f, 0.f, 0.f), bv1 = bv0;
        if (bn + bc4 < N)
            bv0 = *(const float4*)&Bm[(size_t)(k0 + br) * N + bn + bc4];
        if (bn + bc4 + 4 < N)
            bv1 = *(const float4*)&Bm[(size_t)(k0 + br) * N + bn + bc4 + 4];

        __syncthreads();
        As[ar][ac4 + 0] = f2tf(av0.x); As[ar][ac4 + 1] = f2tf(av0.y);
        As[ar][ac4 + 2] = f2tf(av0.z); As[ar][ac4 + 3] = f2tf(av0.w);
        As[ar][ac4 + 4] = f2tf(av1.x); As[ar][ac4 + 5] = f2tf(av1.y);
        As[ar][ac4 + 6] = f2tf(av1.z); As[ar][ac4 + 7] = f2tf(av1.w);
        Bs[br][bc4 + 0] = f2tf(bv0.x); Bs[br][bc4 + 1] = f2tf(bv0.y);
        Bs[br][bc4 + 2] = f2tf(bv0.z); Bs[br][bc4 + 3] = f2tf(bv0.w);
        Bs[br][bc4 + 4] = f2tf(bv1.x); Bs[br][bc4 + 5] = f2tf(bv1.y);
        Bs[br][bc4 + 6] = f2tf(bv1.z); Bs[br][bc4 + 7] = f2tf(bv1.w);
        __syncthreads();

#pragma unroll
        for (int kk = 0; kk < 16; kk += 8) {
            float a[4][4], b[4][2];
#pragma unroll
            for (int mi = 0; mi < 4; mi++) {
                int row = wm + 16 * mi;
                a[mi][0] = As[row + r][kk + c];
                a[mi][1] = As[row + r + 8][kk + c];
                a[mi][2] = As[row + r][kk + c + 4];
                a[mi][3] = As[row + r + 8][kk + c + 4];
            }
#pragma unroll
            for (int ni = 0; ni < 4; ni++) {
                int col = wn + 8 * ni + r;
                b[ni][0] = Bs[kk + c][col];
                b[ni][1] = Bs[kk + c + 4][col];
            }
#pragma unroll
            for (int mi = 0; mi < 4; mi++)
#pragma unroll
                for (int ni = 0; ni < 4; ni++)
                    mma8(acc[mi][ni][0], acc[mi][ni][1], acc[mi][ni][2], acc[mi][ni][3],
                         a[mi][0], a[mi][1], a[mi][2], a[mi][3], b[ni][0], b[ni][1]);
        }
    }

#pragma unroll
    for (int mi = 0; mi < 4; mi++) {
        int row0 = bm + wm + 16 * mi + r;
#pragma unroll
        for (int ni = 0; ni < 4; ni++) {
            int col0 = bn + wn + 8 * ni + 2 * c;
            if (col0 < N) {
                C[(size_t)row0 * N + col0]       = acc[mi][ni][0] + bias[col0];
                C[(size_t)(row0 + 8) * N + col0] = acc[mi][ni][2] + bias[col0];
            }
            if (col0 + 1 < N) {
                C[(size_t)row0 * N + col0 + 1]       = acc[mi][ni][1] + bias[col0 + 1];
                C[(size_t)(row0 + 8) * N + col0 + 1] = acc[mi][ni][3] + bias[col0 + 1];
            }
        }
    }
}

// ---------------- small kernels ----------------
__global__ void rmsnorm_kernel(float* __restrict__ buf, const float* __restrict__ w,
                               int stride)
{
    const int row = blockIdx.x;
    const int tid = threadIdx.x;
    float v = buf[(size_t)row * stride + tid];
    float s = v * v;
#pragma unroll
    for (int o = 16; o; o >>= 1) s += __shfl_xor_sync(0xffffffffu, s, o);
    __shared__ float ws[4];
    if ((tid & 31) == 0) ws[tid >> 5] = s;
    __syncthreads();
    float tot = ws[0] + ws[1] + ws[2] + ws[3];
    float rr = rsqrtf(tot / (float)blockDim.x + 1e-8f);
    buf[(size_t)row * stride + tid] = w[tid] * v * rr;
}

__global__ void rope_kernel(float* __restrict__ buf, const int* __restrict__ pos,
                            int stride, int col_off, int hd)
{
    const int row = blockIdx.x;
    const int tid = threadIdx.x;
    const int half = hd >> 1;
    const int h = tid / half, i = tid % half;
    float p = (float)pos[row];
    float freq = powf(10000.0f, -2.0f * (float)i / (float)hd);
    float ang = p * freq;
    float sn, cs;
    sincosf(ang, &sn, &cs);
    size_t base = (size_t)row * stride + col_off + h * hd + 2 * i;
    float xe = buf[base], xo = buf[base + 1];
    buf[base]     = xe * cs - xo * sn;
    buf[base + 1] = xe * sn + xo * cs;
}

__global__ void repack_kernel(const float* __restrict__ q, const float* __restrict__ kv,
                              const float* __restrict__ ckv,
                              float* __restrict__ Qo, float* __restrict__ Ko,
                              float* __restrict__ Vo)
{
    const int bhs = blockIdx.x;
    const int d   = threadIdx.x;
    const int s   = bhs & (S_ - 1);
    const int bh  = bhs >> 11;
    const int h   = bh & 7;
    const int b   = bh >> 3;
    const size_t row = (size_t)b * S_ + s;
    const size_t o128 = (size_t)bhs * 128, o256 = (size_t)bhs * 256;

    Qo[o128 + d] = (d < 96) ? q[row * 1024 + h * 96 + d]
                            : q[row * 1024 + 768 + h * 32 + (d - 96)];
    Ko[o128 + d] = (d < 64) ? kv[row * 2560 + h * 64 + d]
                            : ckv[row * 192 + 128 + (d - 64)];
    Vo[o256 + d]       = kv[row * 2560 + 512 + (size_t)h * 256 + d];
    Vo[o256 + 128 + d] = kv[row * 2560 + 512 + (size_t)h * 256 + 128 + d];
}

// ---------------- tf32 flash attention ----------------
// CTA: 256 thr (8 warps). BM=64 q-rows, BN=64 keys/iter, VD=256.
// S phase: warp (wm = wid>>1) rows 16*wm, (wn = wid&1) cols 32*wn.
// PV phase: warp rows 16*wm, out cols 128*wn.
#define SQ_STRIDE 132
#define SV_STRIDE 264
#define SP_STRIDE 68

__global__ void __launch_bounds__(256) flash_tf32(
    const float* __restrict__ Q, const float* __restrict__ K,
    const float* __restrict__ V, float* __restrict__ O)
{
    extern __shared__ float sm[];
    float* sQ  = sm;                       // 64*132
    float* sK  = sQ + 64 * SQ_STRIDE;      // 64*132
    float* sV  = sK + 64 * SQ_STRIDE;      // 64*264
    float* sP  = sV + 64 * SV_STRIDE;      // 64*68
    float* rMax = sP + 64 * SP_STRIDE;     // 2*64
    float* rSum = rMax + 128;              // 2*64

    const int tid  = threadIdx.x;
    const int wid  = tid >> 5;
    const int lane = tid & 31;
    const int wm   = wid >> 1;      // 0..3
    const int wn   = wid & 1;       // 0..1
    const int r    = lane >> 2;
    const int c    = lane & 3;
    const int bh   = blockIdx.y;
    const int qt   = blockIdx.x;
    const float scale = 0.08838834764831845f;   // 1/sqrt(128)

    // load Q tile (scaled, tf32-rounded)
    const float* Qg = Q + ((size_t)bh * S_ + qt * 64) * QD;
    for (int i = tid; i < 64 * 32; i += 256) {
        int row = i >> 5, col = (i & 31) << 2;
        float4 v = *(const float4*)&Qg[row * QD + col];
        float* d = &sQ[row * SQ_STRIDE + col];
        d[0] = f2tf(v.x * scale); d[1] = f2tf(v.y * scale);
        d[2] = f2tf(v.z * scale); d[3] = f2tf(v.w * scale);
    }

    float o[16][4];
#pragma unroll
    for (int i = 0; i < 16; i++)
#pragma unroll
        for (int j = 0; j < 4; j++) o[i][j] = 0.f;
    float m0 = -1e30f, m1 = -1e30f, l0 = 0.f, l1 = 0.f;

    const int row0 = 16 * wm + r;       // tile-local rows this thread owns
    const int row1 = row0 + 8;

    for (int kt = 0; kt < S_ / 64; kt++) {
        __syncthreads();
        const float* Kg = K + ((size_t)bh * S_ + kt * 64) * QD;
        for (int i = tid; i < 64 * 32; i += 256) {
            int row = i >> 5, col = (i & 31) << 2;
            float4 v = *(const float4*)&Kg[row * QD + col];
            float* d = &sK[row * SQ_STRIDE + col];
            d[0] = f2tf(v.x); d[1] = f2tf(v.y); d[2] = f2tf(v.z); d[3] = f2tf(v.w);
        }
        const float* Vg = V + ((size_t)bh * S_ + kt * 64) * VD;
        for (int i = tid; i < 64 * 64; i += 256) {
            int row = i >> 6, col = (i & 63) << 2;
            float4 v = *(const float4*)&Vg[row * VD + col];
            float* d = &sV[row * SV_STRIDE + col];
            d[0] = f2tf(v.x); d[1] = f2tf(v.y); d[2] = f2tf(v.z); d[3] = f2tf(v.w);
        }
        __syncthreads();

        // ---- S = Q @ K^T (warp: 16 x 32) ----
        float s[4][4];
#pragma unroll
        for (int ni = 0; ni < 4; ni++)
#pragma unroll
            for (int j = 0; j < 4; j++) s[ni][j] = 0.f;

#pragma unroll
        for (int kk = 0; kk < 128; kk += 8) {
            float a0 = sQ[(16 * wm + r) * SQ_STRIDE + kk + c];
            float a1 = sQ[(16 * wm + r + 8) * SQ_STRIDE + kk + c];
            float a2 = sQ[(16 * wm + r) * SQ_STRIDE + kk + c + 4];
            float a3 = sQ[(16 * wm + r + 8) * SQ_STRIDE + kk + c + 4];
#pragma unroll
            for (int ni = 0; ni < 4; ni++) {
                int key = 32 * wn + 8 * ni + r;
                float b0 = sK[key * SQ_STRIDE + kk + c];
                float b1 = sK[key * SQ_STRIDE + kk + c + 4];
                mma8(s[ni][0], s[ni][1], s[ni][2], s[ni][3], a0, a1, a2, a3, b0, b1);
            }
        }

        // ---- online softmax ----
        float tmax0 = -1e30f, tmax1 = -1e30f;
#pragma unroll
        for (int ni = 0; ni < 4; ni++) {
            tmax0 = fmaxf(tmax0, fmaxf(s[ni][0], s[ni][1]));
            tmax1 = fmaxf(tmax1, fmaxf(s[ni][2], s[ni][3]));
        }
        tmax0 = fmaxf(tmax0, __shfl_xor_sync(0xffffffffu, tmax0, 1));
        tmax0 = fmaxf(tmax0, __shfl_xor_sync(0xffffffffu, tmax0, 2));
        tmax1 = fmaxf(tmax1, __shfl_xor_sync(0xffffffffu, tmax1, 1));
        tmax1 = fmaxf(tmax1, __shfl_xor_sync(0xffffffffu, tmax1, 2));
        if (c == 0) {
            rMax[wn * 64 + row0] = tmax0;
            rMax[wn * 64 + row1] = tmax1;
        }
        __syncthreads();
        float tile0 = fmaxf(rMax[row0], rMax[64 + row0]);
        float tile1 = fmaxf(rMax[row1], rMax[64 + row1]);
        float mn0 = fmaxf(m0, tile0), mn1 = fmaxf(m1, tile1);
        float alpha0 = __expf(m0 - mn0), alpha1 = __expf(m1 - mn1);

        float ps0 = 0.f, ps1 = 0.f;
#pragma unroll
        for (int ni = 0; ni < 4; ni++) {
            int colb = 32 * wn + 8 * ni + 2 * c;
            float p0 = __expf(s[ni][0] - mn0);
            float p1 = __expf(s[ni][1] - mn0);
            float p2 = __expf(s[ni][2] - mn1);
            float p3 = __expf(s[ni][3] - mn1);
            ps0 += p0 + p1; ps1 += p2 + p3;
            sP[row0 * SP_STRIDE + colb]     = f2tf(p0);
            sP[row0 * SP_STRIDE + colb + 1] = f2tf(p1);
            sP[row1 * SP_STRIDE + colb]     = f2tf(p2);
            sP[row1 * SP_STRIDE + colb + 1] = f2tf(p3);
        }
        ps0 += __shfl_xor_sync(0xffffffffu, ps0, 1);
        ps0 += __shfl_xor_sync(0xffffffffu, ps0, 2);
        ps1 += __shfl_xor_sync(0xffffffffu, ps1, 1);
        ps1 += __shfl_xor_sync(0xffffffffu, ps1, 2);
        if (c == 0) {
            rSum[wn * 64 + row0] = ps0;
            rSum[wn * 64 + row1] = ps1;
        }
        __syncthreads();
        l0 = l0 * alpha0 + rSum[row0] + rSum[64 + row0];
        l1 = l1 * alpha1 + rSum[row1] + rSum[64 + row1];
        m0 = mn0; m1 = mn1;

        // rescale O
#pragma unroll
        for (int nf = 0; nf < 16; nf++) {
            o[nf][0] *= alpha0; o[nf][1] *= alpha0;
            o[nf][2] *= alpha1; o[nf][3] *= alpha1;
        }

        // ---- PV: warp rows 16*wm, out cols 128*wn ----
#pragma unroll
        for (int kf = 0; kf < 8; kf++) {
            float a0 = sP[(16 * wm + r) * SP_STRIDE + 8 * kf + c];
            float a1 = sP[(16 * wm + r + 8) * SP_STRIDE + 8 * kf + c];
            float a2 = sP[(16 * wm + r) * SP_STRIDE + 8 * kf + c + 4];
            float a3 = sP[(16 * wm + r + 8) * SP_STRIDE + 8 * kf + c + 4];
#pragma unroll
            for (int nf = 0; nf < 16; nf++) {
                int col = 128 * wn + 8 * nf + r;
                float b0 = sV[(8 * kf + c) * SV_STRIDE + col];
                float b1 = sV[(8 * kf + c + 4) * SV_STRIDE + col];
                mma8(o[nf][0], o[nf][1], o[nf][2], o[nf][3], a0, a1, a2, a3, b0, b1);
            }
        }
    }

    // ---- write out: [b, s, h*256] ----
    const float inv0 = 1.0f / l0, inv1 = 1.0f / l1;
    const int b = bh >> 3, h = bh & 7;
    const size_t gr0 = ((size_t)b * S_ + qt * 64 + row0) * 2048 + h * 256;
    const size_t gr1 = ((size_t)b * S_ + qt * 64 + row1) * 2048 + h * 256;
#pragma unroll
    for (int nf = 0; nf < 16; nf++) {
        int col = 128 * wn + 8 * nf + 2 * c;
        O[gr0 + col]     = o[nf][0] * inv0;
        O[gr0 + col + 1] = o[nf][1] * inv0;
        O[gr1 + col]     = o[nf][2] * inv1;
        O[gr1 + col + 1] = o[nf][3] * inv1;
    }
}

// ---------------- launch ----------------
extern "C" void kernel_launch(void* const* d_in, const int* in_sizes, int n_in,
                              void* d_out, int out_size)
{
    const float* x         = (const float*)d_in[0];
    const int*   pos       = (const int*)  d_in[1];
    const float* w_dq_w    = (const float*)d_in[2];
    const float* w_dq_b    = (const float*)d_in[3];
    const float* q_norm_w  = (const float*)d_in[4];
    const float* w_uq_w    = (const float*)d_in[5];
    const float* w_uq_b    = (const float*)d_in[6];
    const float* w_dkv_w   = (const float*)d_in[7];
    const float* w_dkv_b   = (const float*)d_in[8];
    const float* kv_norm_w = (const float*)d_in[9];
    const float* w_ukv_w   = (const float*)d_in[10];
    const float* w_ukv_b   = (const float*)d_in[11];
    const float* w_o_w     = (const float*)d_in[12];
    const float* w_o_b     = (const float*)d_in[13];
    float* out = (float*)d_out;

    float *cq, *ckv, *q, *kv, *Qs, *Ks, *Vs, *attn;
    cudaGetSymbolAddress((void**)&cq,   g_cq);
    cudaGetSymbolAddress((void**)&ckv,  g_ckv);
    cudaGetSymbolAddress((void**)&q,    g_q);
    cudaGetSymbolAddress((void**)&kv,   g_kv);
    cudaGetSymbolAddress((void**)&Qs,   g_Qs);
    cudaGetSymbolAddress((void**)&Ks,   g_Ks);
    cudaGetSymbolAddress((void**)&Vs,   g_Vs);
    cudaGetSymbolAddress((void**)&attn, g_attn);

    const int M = MROWS;

    // down-projections (fp32 for precision headroom)
    sgemm_bias<<<dim3(1, 32), 256>>>(x, w_dq_w,  w_dq_b,  cq,  M, 128, 1024, 1024);
    sgemm_bias<<<dim3(2, 32), 256>>>(x, w_dkv_w, w_dkv_b, ckv, M, 192, 1024, 1024);

    rmsnorm_kernel<<<M, 128>>>(cq,  q_norm_w,  128);
    rmsnorm_kernel<<<M, 128>>>(ckv, kv_norm_w, 192);
    rope_kernel<<<M, 32>>>(ckv, pos, 192, 128, 64);

    // up-projections (tf32 tensor cores)
    gemm_tf32<<<dim3(8, 32), 256>>>(cq,  w_uq_w,  w_uq_b,  q,  M, 1024, 128, 128);
    rope_kernel<<<M, 128>>>(q, pos, 1024, 768, 32);
    gemm_tf32<<<dim3(20, 32), 256>>>(ckv, w_ukv_w, w_ukv_b, kv, M, 2560, 128, 192);

    repack_kernel<<<B_ * NH_ * S_, 128>>>(q, kv, ckv, Qs, Ks, Vs);

    // attention (tf32 tensor cores)
    const int smem = (64 * SQ_STRIDE * 2 + 64 * SV_STRIDE + 64 * SP_STRIDE + 256) * 4;
    cudaFuncSetAttribute(flash_tf32, cudaFuncAttributeMaxDynamicSharedMemorySize, smem);
    flash_tf32<<<dim3(S_ / 64, B_ * NH_), 256, smem>>>(Qs, Ks, Vs, attn);

    // output projection (tf32)
    gemm_tf32<<<dim3(8, 32), 256>>>(attn, w_o_w, w_o_b, out, M, 1024, 2048, 2048);
}